// round 4
// baseline (speedup 1.0000x reference)
#include <cuda_runtime.h>
#include <math.h>

#define T_   8192
#define DIN  2048
#define D_   512
#define H_   512
#define H3_  1536
#define A_   18

#define NC   64          // recurrence CTAs (single wave: 64 < 148 SMs)
#define HC   (H_/NC)     // 8 hidden units per CTA (one warp each)
#define CNT_STRIDE 64    // counter padding: 256B apart -> distinct L2 slices

// ---------------- scratch (device globals: no allocation allowed) ----------
__device__ float g_z1[(size_t)T_ * D_];          // 16 MB
__device__ float g_z2[(size_t)T_ * D_];          // 16 MB
__device__ float g_X [(size_t)T_ * H3_];         // 48 MB
__device__ float g_seq[(size_t)T_ * H_];         // 16 MB
__device__ __align__(16) float g_h[2][H_];       // double-buffered h (plain fp32)
__device__ unsigned g_cnt[8 * CNT_STRIDE];       // 8 step counters, padded

// ---------------- memory-order helpers -------------------------------------
__device__ __forceinline__ unsigned ld_acquire_u32(const unsigned* p) {
    unsigned v;
    asm volatile("ld.acquire.gpu.global.u32 %0, [%1];" : "=r"(v) : "l"(p) : "memory");
    return v;
}
__device__ __forceinline__ void red_release_add(unsigned* p, unsigned v) {
    asm volatile("red.release.gpu.global.add.u32 [%0], %1;" :: "l"(p), "r"(v) : "memory");
}

// ---------------- fp32 tiled GEMM: C = act(A[M,K] @ B[K,N] + bias) ---------
// doInit: block (0,0) additionally resets counters + h_{-1} buffer.
__global__ __launch_bounds__(256) void gemm_kernel(
    const float* __restrict__ A, const float* __restrict__ B,
    const float* __restrict__ bias, float* __restrict__ C,
    int M, int N, int K, int doRelu,
    const float* __restrict__ h0, int doInit)
{
    __shared__ float As[16][64];
    __shared__ float Bs[16][64];
    const int tid = threadIdx.x;

    if (doInit && blockIdx.x == 0 && blockIdx.y == 0) {
        if (tid < 8) g_cnt[tid * CNT_STRIDE] = 0;
        g_h[1][tid]       = h0[tid];         // h_{-1} lives in buf 1 (step 0 reads (0-1)&1 = 1)
        g_h[1][tid + 256] = h0[tid + 256];
    }

    const int bm = blockIdx.y * 64;
    const int bn = blockIdx.x * 64;
    const int tx = tid & 15, ty = tid >> 4;

    const int aRow = tid >> 2;            // 0..63
    const int aK   = (tid & 3) << 2;      // 0,4,8,12
    const int bRow = tid >> 4;            // 0..15
    const int bCol = (tid & 15) << 2;     // 0..60

    const float* Aptr = A + (size_t)(bm + aRow) * K + aK;
    const float* Bptr = B + (size_t)bRow * N + bn + bCol;

    float acc[4][4];
#pragma unroll
    for (int i = 0; i < 4; i++)
#pragma unroll
        for (int j = 0; j < 4; j++) acc[i][j] = 0.f;

    for (int k0 = 0; k0 < K; k0 += 16) {
        float4 a4 = *(const float4*)(Aptr + k0);
        float4 b4 = *(const float4*)(Bptr + (size_t)k0 * N);
        As[aK + 0][aRow] = a4.x;
        As[aK + 1][aRow] = a4.y;
        As[aK + 2][aRow] = a4.z;
        As[aK + 3][aRow] = a4.w;
        *(float4*)&Bs[bRow][bCol] = b4;
        __syncthreads();
#pragma unroll
        for (int k = 0; k < 16; k++) {
            float4 av = *(const float4*)&As[k][ty << 2];
            float4 bv = *(const float4*)&Bs[k][tx << 2];
            float a_[4] = {av.x, av.y, av.z, av.w};
            float b_[4] = {bv.x, bv.y, bv.z, bv.w};
#pragma unroll
            for (int i = 0; i < 4; i++)
#pragma unroll
                for (int j = 0; j < 4; j++)
                    acc[i][j] = fmaf(a_[i], b_[j], acc[i][j]);
        }
        __syncthreads();
    }

#pragma unroll
    for (int i = 0; i < 4; i++) {
        int m = bm + (ty << 2) + i;
#pragma unroll
        for (int j = 0; j < 4; j++) {
            int n = bn + (tx << 2) + j;
            float v = acc[i][j] + bias[n];
            if (doRelu) v = fmaxf(v, 0.f);
            C[(size_t)m * N + n] = v;
        }
    }
}

// ---------------- GRU recurrence: 64 persistent CTAs ------------------------
// Detect plane (tiny): 8 padded counters, red.release +1 per producer warp,
// acquire-polled 8x4B per sweep by warp 0 only.
// Data plane (read once): warp 0 loads the 2KB h vector as float4 __ldcg and
// stages it to shared; all warps compute from shared.
// Single-buffered shared is safe: passing the poll for step t implies every
// warp chip-wide incremented for step t-1, and release orders each producer's
// shared-reads before its increment.
__global__ __launch_bounds__(256) void recur_kernel(
    const float* __restrict__ Ug,    // [H, 3H] row-major
    const float* __restrict__ brec,  // [3H]  (bg row 1)
    const float* __restrict__ X,     // [T, 3H]
    float* __restrict__ seq,         // [T, H]
    float* __restrict__ hT_out)      // [H]
{
    __shared__ __align__(16) float hs[H_];
    const int tid  = threadIdx.x;
    const int lane = tid & 31;
    const int w    = tid >> 5;                 // warp 0..7
    const int j    = blockIdx.x * HC + w;      // hidden unit owned by this warp

    // Stage this warp's Ug columns into registers: lane covers k = lane+32*kk
    float wz[16], wr[16], wh[16];
#pragma unroll
    for (int kk = 0; kk < 16; kk++) {
        const float* row = Ug + (size_t)(lane + (kk << 5)) * H3_;
        wz[kk] = row[j];
        wr[kk] = row[j + H_];
        wh[kk] = row[j + 2 * H_];
    }
    const float bz = brec[j], br = brec[j + H_], bh = brec[j + 2 * H_];

    // lane 0 holds the X row values for this unit (prefetched)
    float xz = 0.f, xr = 0.f, xh = 0.f;
    if (lane == 0) { xz = X[j]; xr = X[j + H_]; xh = X[j + 2 * H_]; }

    unsigned* myCnt = &g_cnt[w * CNT_STRIDE];

    for (int t = 0; t < T_; t++) {
        if (w == 0) {
            if (t > 0) {
                const unsigned target = 64u * (unsigned)t;
                const unsigned* cp = (lane < 8) ? &g_cnt[lane * CNT_STRIDE] : &g_cnt[0];
                for (;;) {
                    unsigned c = ld_acquire_u32(cp);
                    if (lane >= 8) c = 0xFFFFFFFFu;
                    if (__ballot_sync(0xffffffffu, c >= target) == 0xffffffffu) break;
                }
            }
            // stage h_{t-1} (2KB) once: coalesced float4 L2 reads
            const float4* src = (const float4*)g_h[(t - 1) & 1];
            float4* dst = (float4*)hs;
#pragma unroll
            for (int i = 0; i < 4; i++)
                dst[(i << 5) + lane] = __ldcg(src + (i << 5) + lane);
        }
        __syncthreads();

        // rec dot products: 3 gates, 16 k's per lane (2 accumulators per gate)
        float az0 = 0.f, ar0 = 0.f, ah0 = 0.f;
        float az1 = 0.f, ar1 = 0.f, ah1 = 0.f;
#pragma unroll
        for (int kk = 0; kk < 16; kk += 2) {
            float h0v = hs[lane + (kk << 5)];
            float h1v = hs[lane + ((kk + 1) << 5)];
            az0 = fmaf(h0v, wz[kk], az0);   az1 = fmaf(h1v, wz[kk + 1], az1);
            ar0 = fmaf(h0v, wr[kk], ar0);   ar1 = fmaf(h1v, wr[kk + 1], ar1);
            ah0 = fmaf(h0v, wh[kk], ah0);   ah1 = fmaf(h1v, wh[kk + 1], ah1);
        }
        float az = az0 + az1, ar = ar0 + ar1, ah = ah0 + ah1;
#pragma unroll
        for (int off = 16; off; off >>= 1) {
            az += __shfl_xor_sync(0xffffffffu, az, off);
            ar += __shfl_xor_sync(0xffffffffu, ar, off);
            ah += __shfl_xor_sync(0xffffffffu, ah, off);
        }

        if (lane == 0) {
            float zt = __fdividef(1.f, 1.f + __expf(-(xz + az + bz)));
            float rt = __fdividef(1.f, 1.f + __expf(-(xr + ar + br)));
            float hh = __fdividef(1.f, 1.f + __expf(-(xh + rt * (ah + bh))));
            float hp = hs[j];
            float hn = fmaf(zt, hp - hh, hh);   // zt*hp + (1-zt)*hh
            seq[(size_t)t * H_ + j] = hn;
            __stcg(&g_h[t & 1][j], hn);          // data store (L2)
            red_release_add(myCnt, 1u);          // ordered flag increment
            if (t == T_ - 1) hT_out[j] = hn;
            if (t + 1 < T_) {   // prefetch next X row (overlaps next poll)
                const float* xp = X + (size_t)(t + 1) * H3_;
                xz = __ldcs(xp + j); xr = __ldcs(xp + j + H_); xh = __ldcs(xp + j + 2 * H_);
            }
        }
        // no trailing barrier: next-step staging by warp 0 is gated by the
        // global poll, which implies this CTA's warps finished reading hs.
    }
}

// ---------------- heads: softmax policy (18) + value, one warp per row -----
__global__ __launch_bounds__(256) void head_kernel(
    const float* __restrict__ seq, const float* __restrict__ Wp,
    const float* __restrict__ bp,  const float* __restrict__ Wv,
    const float* __restrict__ bv,  float* __restrict__ out)
{
    int row  = blockIdx.x * (blockDim.x >> 5) + (threadIdx.x >> 5);
    int lane = threadIdx.x & 31;
    if (row >= T_) return;
    const float* h = seq + (size_t)row * H_;

    const float* wcol = (lane < 18) ? (Wp + lane) : Wv;
    const int stride  = (lane < 18) ? A_ : 1;
    float acc = 0.f;
    if (lane < 19) {
#pragma unroll 8
        for (int k = 0; k < H_; k++)
            acc = fmaf(__ldg(h + k), __ldg(wcol + k * stride), acc);
    }

    const float NEG_INF = __int_as_float(0xff800000);
    float logit = (lane < 18) ? acc + bp[lane] : NEG_INF;
    float m = logit;
#pragma unroll
    for (int off = 16; off; off >>= 1)
        m = fmaxf(m, __shfl_xor_sync(0xffffffffu, m, off));
    float e = (lane < 18) ? __expf(logit - m) : 0.f;
    float s = e;
#pragma unroll
    for (int off = 16; off; off >>= 1)
        s += __shfl_xor_sync(0xffffffffu, s, off);

    if (lane < 18)  out[(size_t)row * A_ + lane] = e / s;
    if (lane == 18) out[(size_t)T_ * A_ + row]   = acc + bv[0];
}

// ---------------- launch --------------------------------------------------
extern "C" void kernel_launch(void* const* d_in, const int* in_sizes, int n_in,
                              void* d_out, int out_size)
{
    (void)in_sizes; (void)n_in; (void)out_size;
    const float* x  = (const float*)d_in[0];
    const float* h0 = (const float*)d_in[1];
    const float* W1 = (const float*)d_in[2];
    const float* b1 = (const float*)d_in[3];
    const float* W2 = (const float*)d_in[4];
    const float* b2 = (const float*)d_in[5];
    const float* Wg = (const float*)d_in[6];
    const float* Ug = (const float*)d_in[7];
    const float* bg = (const float*)d_in[8];
    const float* Wp = (const float*)d_in[9];
    const float* bp = (const float*)d_in[10];
    const float* Wv = (const float*)d_in[11];
    const float* bv = (const float*)d_in[12];
    float* out = (float*)d_out;

    float *z1p, *z2p, *Xp, *seqp;
    cudaGetSymbolAddress((void**)&z1p,  g_z1);
    cudaGetSymbolAddress((void**)&z2p,  g_z2);
    cudaGetSymbolAddress((void**)&Xp,   g_X);
    cudaGetSymbolAddress((void**)&seqp, g_seq);

    gemm_kernel<<<dim3(D_ / 64,  T_ / 64), 256>>>(x,   W1, b1, z1p, T_, D_,  DIN, 1, h0, 1);
    gemm_kernel<<<dim3(D_ / 64,  T_ / 64), 256>>>(z1p, W2, b2, z2p, T_, D_,  D_,  1, h0, 0);
    gemm_kernel<<<dim3(H3_ / 64, T_ / 64), 256>>>(z2p, Wg, bg, Xp,  T_, H3_, D_,  0, h0, 0);
    recur_kernel<<<NC, 256>>>(Ug, bg + H3_, Xp, seqp, out + (size_t)T_ * A_ + T_);
    head_kernel<<<T_ / 8, 256>>>(seqp, Wp, bp, Wv, bv, out);
}